// round 12
// baseline (speedup 1.0000x reference)
#include <cuda_runtime.h>
#include <cuda_fp16.h>
#include <cuda_bf16.h>
#include <math.h>
#include <stdint.h>

// Problem constants
#define BB 512
#define DD 512
#define LL 32
#define HH 300
#define NP 320
#define RS 328
#define ZS 40
#define NPAIR 10
#define CHUNK_H (16 * RS)   // enc chunk halves = 5248
#define CHUNK_B (CHUNK_H * 2)
#define CHUNK_U (CHUNK_B / 16)
#define PAIR_B  (2 * CHUNK_B)
#define W1_U    (2 * CHUNK_U)      // 32 x 328 halves / 8 = 1312 units

// Decoder (split) constants
#define MT2 64               // batch rows per CTA
#define NH2 160              // n-half columns per CTA
#define HRS 168              // half-width stride (halves)
#define HCH_H (16 * HRS)     // 2688
#define HCH_B (HCH_H * 2)    // 5376
#define HPAIR_B (2 * HCH_B)  // 10752
#define HPAIR_U (HPAIR_B / 16) // 672

// Decoder SMEM layout (bytes)
#define D_ZM   0             // 64*40*2   = 5120
#define D_G1   5120          // 64*328*2  = 41984
#define D_W1   47104         // 32*328*2  = 20992
#define D_RING 68096         // 3*10752   = 32256
#define D_B2   100352        // 160*4     = 640
#define D_CW   100992        // 640
#define D_OUT  101632        // 64*4      = 256
#define D_SMEM 101888

// enc1 SMEM layout
#define XRS 520
#define SRS 72
#define SCH_B 2304
#define SCH_U 144
#define SPAIR_B 4608
#define SPAIR_U 288
#define E1_XS   0
#define E1_RING 66560
#define E1_B1   84992
#define E1_SMEM 85248

// enc2 SMEM layout
#define E2_H1   0
#define E2_H2   41984
#define E2_RING 83968
#define E2_ZW   167936
#define E2_B2   214016
#define E2_ZB   215296
#define E2_SMEM 215808
#define ZWS 72

// ---------------------------------------------------------------------------
// Scratch (device globals: allocation-free rule)
// ---------------------------------------------------------------------------
__device__ float  g_z[BB * LL];
__device__ __half g_w1h[LL * RS];            // decoder W1 full width
__device__ __half g_w2hx[2 * 20 * HCH_H];    // decoder W2 [half][20 chunks][16][168]
__device__ __half g_ew1[32 * CHUNK_H];       // qz_w1
__device__ __half g_ew2[20 * CHUNK_H];       // qz_w2
__device__ __half g_zw[NP * ZWS];            // zm|zl
__device__ __half g_xh[BB * XRS];            // x fp16 padded
__device__ __half g_h1h[BB * RS];            // h1 fp16

// ---------------------------------------------------------------------------
// PTX helpers
// ---------------------------------------------------------------------------
__device__ __forceinline__ void ldsm_x4(uint32_t* r, uint32_t addr) {
    asm volatile("ldmatrix.sync.aligned.m8n8.x4.shared.b16 {%0,%1,%2,%3}, [%4];"
                 : "=r"(r[0]), "=r"(r[1]), "=r"(r[2]), "=r"(r[3]) : "r"(addr));
}
__device__ __forceinline__ void ldsm_x4t(uint32_t* r, uint32_t addr) {
    asm volatile("ldmatrix.sync.aligned.m8n8.x4.trans.shared.b16 {%0,%1,%2,%3}, [%4];"
                 : "=r"(r[0]), "=r"(r[1]), "=r"(r[2]), "=r"(r[3]) : "r"(addr));
}
__device__ __forceinline__ void ldsm_x2t(uint32_t* r, uint32_t addr) {
    asm volatile("ldmatrix.sync.aligned.m8n8.x2.trans.shared.b16 {%0,%1}, [%2];"
                 : "=r"(r[0]), "=r"(r[1]) : "r"(addr));
}
__device__ __forceinline__ void mma16(float* d, const uint32_t* a, uint32_t b0, uint32_t b1) {
    asm volatile(
        "mma.sync.aligned.m16n8k16.row.col.f32.f16.f16.f32 "
        "{%0,%1,%2,%3}, {%4,%5,%6,%7}, {%8,%9}, {%0,%1,%2,%3};"
        : "+f"(d[0]), "+f"(d[1]), "+f"(d[2]), "+f"(d[3])
        : "r"(a[0]), "r"(a[1]), "r"(a[2]), "r"(a[3]), "r"(b0), "r"(b1));
}
__device__ __forceinline__ void cp16(uint32_t dst, const void* src) {
    asm volatile("cp.async.cg.shared.global [%0], [%1], 16;" :: "r"(dst), "l"(src));
}
__device__ __forceinline__ void cp_commit() {
    asm volatile("cp.async.commit_group;");
}

// ---------------------------------------------------------------------------
// Pack fp16 images
// ---------------------------------------------------------------------------
__global__ void pack_weights(const float* __restrict__ gen_w1,
                             const float* __restrict__ gen_w2,
                             const float* __restrict__ qz_w1,
                             const float* __restrict__ qz_w2,
                             const float* __restrict__ zm_w,
                             const float* __restrict__ zl_w,
                             const float* __restrict__ x) {
    int idx = blockIdx.x * blockDim.x + threadIdx.x;
    const int S0 = LL * RS;                 // 10496
    const int S1 = S0 + 2 * 20 * HCH_H;     // +107520 = 118016
    const int S2 = S1 + 32 * CHUNK_H;       // +167936 = 285952
    const int S3 = S2 + 20 * CHUNK_H;       // +104960 = 390912
    const int S4 = S3 + NP * ZWS;           // +23040  = 413952
    const int S5 = S4 + BB * XRS;           // +266240 = 680192
    if (idx < S0) {
        int r = idx / RS, c = idx % RS;
        g_w1h[idx] = (c < NP && c < HH) ? __float2half(gen_w1[r * HH + c])
                   : __half(0.f);
    } else if (idx < S1) {
        int i = idx - S0;
        int half = i / (20 * HCH_H);
        int r2 = i % (20 * HCH_H);
        int k = r2 / HRS, cl = r2 % HRS;
        int c = half * NH2 + cl;
        float v = (k < HH && cl < NH2 && c < HH) ? gen_w2[k * HH + c] : 0.f;
        g_w2hx[i] = __float2half(v);
    } else if (idx < S2) {
        int i = idx - S1;
        int k = i / RS, c = i % RS;
        g_ew1[i] = (c < HH) ? __float2half(qz_w1[k * HH + c]) : __half(0.f);
    } else if (idx < S3) {
        int i = idx - S2;
        int k = i / RS, c = i % RS;
        g_ew2[i] = (k < HH && c < HH) ? __float2half(qz_w2[k * HH + c]) : __half(0.f);
    } else if (idx < S4) {
        int i = idx - S3;
        int k = i / ZWS, c = i % ZWS;
        float v = 0.f;
        if (k < HH) {
            if (c < 32) v = zm_w[k * LL + c];
            else if (c < 64) v = zl_w[k * LL + (c - 32)];
        }
        g_zw[i] = __float2half(v);
    } else if (idx < S5) {
        int i = idx - S4;
        int r = i / XRS, c = i % XRS;
        g_xh[i] = (c < DD) ? __float2half(x[r * DD + c]) : __half(0.f);
    }
}

// xmean init: xmean[b, j] = col_b[j]  (decoder halves atomicAdd partials on top)
__global__ void xinit_kernel(const float* __restrict__ col_b, float* __restrict__ xmean) {
    int idx = blockIdx.x * blockDim.x + threadIdx.x;
    if (idx < BB * DD) xmean[idx] = col_b[idx & (DD - 1)];
}

// ---------------------------------------------------------------------------
// enc1 (unchanged from R11): h1 = relu(x @ qz_w1 + b1). Grid (8, 5).
// ---------------------------------------------------------------------------
__global__ void __launch_bounds__(256, 2)
enc1_kernel(const float* __restrict__ qz_b1) {
    extern __shared__ char smc[];
    float* b1s = (float*)(smc + E1_B1);
    const uint32_t xs_a   = (uint32_t)__cvta_generic_to_shared(smc + E1_XS);
    const uint32_t ring_a = (uint32_t)__cvta_generic_to_shared(smc + E1_RING);

    const int tid  = threadIdx.x;
    const int lane = tid & 31;
    const int warp = tid >> 5;
    const int ms   = (warp & 3) * 16;
    const int nq   = warp >> 2;
    const int m0   = blockIdx.x * 64;
    const int nc0  = blockIdx.y * 64;
    const int seg  = lane >> 3, rr = lane & 7;

    {
        const __half* src = g_xh + m0 * XRS;
        for (int u = tid; u < 64 * XRS / 8; u += 256)
            cp16(xs_a + u * 16, src + u * 8);
        cp_commit();
        #pragma unroll
        for (int p = 0; p < 2; p++) {
            for (int u = tid; u < SPAIR_U; u += 256) {
                int ch = u / SCH_U, uu = u % SCH_U;
                int row = uu / 9, c16 = uu % 9;
                const __half* s = g_ew1 + ((p * 2 + ch) * 16 + row) * RS + nc0 + c16 * 8;
                cp16(ring_a + p * SPAIR_B + ch * SCH_B + (row * SRS + c16 * 8) * 2, s);
            }
            cp_commit();
        }
    }
    if (tid < 64) {
        int g = nc0 + tid;
        b1s[tid] = (g < HH) ? qz_b1[g] : 0.f;
    }
    asm volatile("cp.async.wait_group 2;");
    __syncthreads();

    const int a_ro = (seg & 1) * 8 + rr;
    const int a_cb = (seg >> 1) * 8;
    const int b_k  = (seg & 1) * 8 + rr;
    const int b_nb = (seg >> 1) * 8;

    float acc[4][4];
    #pragma unroll
    for (int t = 0; t < 4; t++)
        #pragma unroll
        for (int i = 0; i < 4; i++) acc[t][i] = 0.f;

    for (int ip = 0; ip < 16; ip++) {
        if (ip + 2 < 16) {
            for (int u = tid; u < SPAIR_U; u += 256) {
                int ch = u / SCH_U, uu = u % SCH_U;
                int row = uu / 9, c16 = uu % 9;
                const __half* s = g_ew1 + (((ip + 2) * 2 + ch) * 16 + row) * RS + nc0 + c16 * 8;
                cp16(ring_a + ((ip + 2) & 3) * SPAIR_B + ch * SCH_B + (row * SRS + c16 * 8) * 2, s);
            }
        }
        cp_commit();
        asm volatile("cp.async.wait_group 2;");
        __syncthreads();

        const uint32_t pbase = ring_a + (ip & 3) * SPAIR_B;
        #pragma unroll
        for (int q = 0; q < 2; q++) {
            const int kc = 2 * ip + q;
            uint32_t a[4];
            ldsm_x4(a, xs_a + ((ms + a_ro) * XRS + kc * 16 + a_cb) * 2);
            const uint32_t Bs = pbase + q * SCH_B;
            #pragma unroll
            for (int p2 = 0; p2 < 2; p2++) {
                int n0 = (nq * 4 + 2 * p2) * 8;
                uint32_t b[4];
                ldsm_x4t(b, Bs + (b_k * SRS + n0 + b_nb) * 2);
                mma16(acc[2 * p2],     a, b[0], b[1]);
                mma16(acc[2 * p2 + 1], a, b[2], b[3]);
            }
        }
    }

    {
        int row = ms + (lane >> 2);
        #pragma unroll
        for (int t = 0; t < 4; t++) {
            int cl = (nq * 4 + t) * 8 + 2 * (lane & 3);
            float v0 = fmaxf(acc[t][0] + b1s[cl], 0.f);
            float v1 = fmaxf(acc[t][1] + b1s[cl + 1], 0.f);
            float v2 = fmaxf(acc[t][2] + b1s[cl], 0.f);
            float v3 = fmaxf(acc[t][3] + b1s[cl + 1], 0.f);
            *(__half2*)(g_h1h + (m0 + row) * RS + nc0 + cl)     = __floats2half2_rn(v0, v1);
            *(__half2*)(g_h1h + (m0 + row + 8) * RS + nc0 + cl) = __floats2half2_rn(v2, v3);
        }
    }
}

// ---------------------------------------------------------------------------
// enc2 + heads fused (unchanged from R10/R11)
// ---------------------------------------------------------------------------
__global__ void __launch_bounds__(512, 1)
enc2_heads_kernel(const float* __restrict__ eps,
                  const float* __restrict__ qz_b2,
                  const float* __restrict__ zm_b,
                  const float* __restrict__ zl_b,
                  float* __restrict__ z_out,
                  float* __restrict__ zm_out,
                  float* __restrict__ zl_out) {
    extern __shared__ char smc[];
    float* b2s = (float*)(smc + E2_B2);
    float* zbb = (float*)(smc + E2_ZB);
    float* zbuf = (float*)(smc + E2_RING);
    const uint32_t h1_a   = (uint32_t)__cvta_generic_to_shared(smc + E2_H1);
    const uint32_t h2_a   = (uint32_t)__cvta_generic_to_shared(smc + E2_H2);
    const uint32_t ring_a = (uint32_t)__cvta_generic_to_shared(smc + E2_RING);
    const uint32_t zw_a   = (uint32_t)__cvta_generic_to_shared(smc + E2_ZW);
    __half* h2s = (__half*)(smc + E2_H2);

    const int tid  = threadIdx.x;
    const int lane = tid & 31;
    const int warp = tid >> 5;
    const int ms   = (warp & 3) * 16;
    const int nq   = warp >> 2;
    const int m0   = blockIdx.x * 64;
    const int seg  = lane >> 3, rr = lane & 7;

    {
        const __half* h1src = g_h1h + m0 * RS;
        for (int u = tid; u < 64 * RS / 8; u += 512)
            cp16(h1_a + u * 16, h1src + u * 8);
        cp_commit();
        for (int u = tid; u < NP * ZWS / 8; u += 512)
            cp16(zw_a + u * 16, g_zw + u * 8);
        cp_commit();
        #pragma unroll
        for (int p = 0; p < 2; p++) {
            const __half* src = g_ew2 + p * 2 * CHUNK_H;
            for (int u = tid; u < 2 * CHUNK_U; u += 512)
                cp16(ring_a + p * PAIR_B + u * 16, src + u * 8);
            cp_commit();
        }
    }
    for (int c = tid; c < NP; c += 512)
        b2s[c] = (c < HH) ? qz_b2[c] : 0.f;
    if (tid < 32) zbb[tid] = zm_b[tid];
    else if (tid < 64) zbb[64 + tid - 32] = zl_b[tid - 32];

    asm volatile("cp.async.wait_group 2;");
    __syncthreads();

    const int a_ro = (seg & 1) * 8 + rr;
    const int a_cb = (seg >> 1) * 8;
    const int b_k  = (seg & 1) * 8 + rr;
    const int b_nb = (seg >> 1) * 8;

    float acc[10][4];
    #pragma unroll
    for (int t = 0; t < 10; t++)
        #pragma unroll
        for (int i = 0; i < 4; i++) acc[t][i] = 0.f;

    for (int ip = 0; ip < NPAIR; ip++) {
        if (ip + 2 < NPAIR) {
            const __half* src = g_ew2 + (ip + 2) * 2 * CHUNK_H;
            uint32_t dst = ring_a + ((ip + 2) & 3) * PAIR_B;
            for (int u = tid; u < 2 * CHUNK_U; u += 512)
                cp16(dst + u * 16, src + u * 8);
        }
        cp_commit();
        asm volatile("cp.async.wait_group 2;");
        __syncthreads();

        const uint32_t pbase = ring_a + (ip & 3) * PAIR_B;
        #pragma unroll
        for (int q = 0; q < 2; q++) {
            const int kc = 2 * ip + q;
            if (kc < 19) {
                const uint32_t Bs = pbase + q * CHUNK_B;
                uint32_t a[4];
                ldsm_x4(a, h1_a + ((ms + a_ro) * RS + kc * 16 + a_cb) * 2);
                #pragma unroll
                for (int p = 0; p < 5; p++) {
                    int n0 = (nq * 10 + 2 * p) * 8;
                    uint32_t b[4];
                    ldsm_x4t(b, Bs + (b_k * RS + n0 + b_nb) * 2);
                    mma16(acc[2 * p],     a, b[0], b[1]);
                    mma16(acc[2 * p + 1], a, b[2], b[3]);
                }
            }
        }
    }

    {
        int row = ms + (lane >> 2);
        #pragma unroll
        for (int t = 0; t < 10; t++) {
            int c = (nq * 10 + t) * 8 + 2 * (lane & 3);
            float v0 = fmaxf(acc[t][0] + b2s[c], 0.f);
            float v1 = fmaxf(acc[t][1] + b2s[c + 1], 0.f);
            float v2 = fmaxf(acc[t][2] + b2s[c], 0.f);
            float v3 = fmaxf(acc[t][3] + b2s[c + 1], 0.f);
            *(__half2*)(h2s + row * RS + c)       = __floats2half2_rn(v0, v1);
            *(__half2*)(h2s + (row + 8) * RS + c) = __floats2half2_rn(v2, v3);
        }
    }
    __syncthreads();

    float ah[2][4];
    #pragma unroll
    for (int t = 0; t < 2; t++)
        #pragma unroll
        for (int i = 0; i < 4; i++) ah[t][i] = 0.f;
    for (int ks = 0; ks < 19; ks++) {
        uint32_t a[4];
        ldsm_x4(a, h2_a + ((ms + a_ro) * RS + ks * 16 + a_cb) * 2);
        int n0 = nq * 16;
        uint32_t b[4];
        ldsm_x4t(b, zw_a + ((ks * 16 + b_k) * ZWS + n0 + b_nb) * 2);
        mma16(ah[0], a, b[0], b[1]);
        mma16(ah[1], a, b[2], b[3]);
    }
    __syncthreads();

    {
        int row = ms + (lane >> 2);
        #pragma unroll
        for (int t = 0; t < 2; t++) {
            int c = nq * 16 + t * 8 + 2 * (lane & 3);
            zbuf[row * 68 + c]           = ah[t][0];
            zbuf[row * 68 + c + 1]       = ah[t][1];
            zbuf[(row + 8) * 68 + c]     = ah[t][2];
            zbuf[(row + 8) * 68 + c + 1] = ah[t][3];
        }
    }
    __syncthreads();

    for (int i = tid; i < 64 * LL; i += 512) {
        int r = i >> 5, l = i & 31;
        float zm = zbuf[r * 68 + l] + zbb[l];
        float zl = zbuf[r * 68 + 32 + l] + zbb[64 + l];
        int o = (m0 + r) * LL + l;
        float zv = zm + eps[o] * expf(0.5f * zl);
        zm_out[o] = zm;
        zl_out[o] = zl;
        z_out[o]  = zv;
        g_z[o]    = zv;
    }
}

// ---------------------------------------------------------------------------
// Split decoder: CTA = (64-batch tile, column j, n-half). 256 threads,
// 2 CTAs/SM. 8 warps = 2m (32 rows each) x 4n (5 n8-tiles each).
// gemm1 computes full G1 (two 160-col passes); gemm2 covers this CTA's n-half.
// Partial x_rec atomicAdd'ed onto col_b-initialized xmean.
// ---------------------------------------------------------------------------
__global__ void __launch_bounds__(256, 2)
decoder_kernel(const float* __restrict__ Wmask,
               const float* __restrict__ gen_b2,
               const float* __restrict__ col_w,
               float* __restrict__ xmean) {
    extern __shared__ char smc[];
    __half* Zms  = (__half*)(smc + D_ZM);
    __half* G1s  = (__half*)(smc + D_G1);
    float*  b2s  = (float*)(smc + D_B2);
    float*  cws  = (float*)(smc + D_CW);
    float*  outs = (float*)(smc + D_OUT);

    const int tid  = threadIdx.x;
    const int lane = tid & 31;
    const int warp = tid >> 5;
    const int r0   = (warp & 1) * 32;      // m-stripe (2 m16 tiles)
    const int ng   = warp >> 1;            // n-group (0..3), 5 n8-tiles
    const int b0   = blockIdx.x * MT2;
    const int j    = blockIdx.y;
    const int half = blockIdx.z;
    const int seg  = lane >> 3, rr = lane & 7;

    const uint32_t zms_a  = (uint32_t)__cvta_generic_to_shared(smc + D_ZM);
    const uint32_t g1s_a  = (uint32_t)__cvta_generic_to_shared(smc + D_G1);
    const uint32_t w1s_a  = (uint32_t)__cvta_generic_to_shared(smc + D_W1);
    const uint32_t ring_a = (uint32_t)__cvta_generic_to_shared(smc + D_RING);

    const __half* w2base = g_w2hx + half * (20 * HCH_H);

    // prologue: W1 (group), W2 pair0 (group)
    for (int u = tid; u < W1_U; u += 256)
        cp16(w1s_a + u * 16, g_w1h + u * 8);
    cp_commit();
    for (int u = tid; u < HPAIR_U; u += 256)
        cp16(ring_a + u * 16, w2base + u * 8);
    cp_commit();

    // stage masked z, b2/cw (n-half slice), init outs
    for (int idx = tid; idx < MT2 * LL; idx += 256) {
        int bl = idx >> 5, l = idx & 31;
        float v = g_z[(b0 + bl) * LL + l] * __ldg(Wmask + j * LL + l);
        Zms[bl * ZS + l] = __float2half(v);
    }
    for (int cl = tid; cl < NH2; cl += 256) {
        int c = half * NH2 + cl;
        b2s[cl] = (c < HH) ? __ldg(gen_b2 + c) : 0.f;
        cws[cl] = (c < HH) ? __ldg(col_w + j * HH + c) : 0.f;
    }
    if (tid < MT2) outs[tid] = 0.f;

    asm volatile("cp.async.wait_group 1;");   // W1 landed
    __syncthreads();

    const int a_ro = (seg & 1) * 8 + rr;
    const int a_cb = (seg >> 1) * 8;
    const int b_k  = (seg & 1) * 8 + rr;
    const int b_nb = (seg >> 1) * 8;
    const int b_k2 = ((lane >> 3) & 1) * 8 + rr;

    float acc[2][5][4];
    #pragma unroll
    for (int m = 0; m < 2; m++)
        #pragma unroll
        for (int t = 0; t < 5; t++)
            #pragma unroll
            for (int i = 0; i < 4; i++) acc[m][t][i] = 0.f;

    // ---- gemm1: full G1 in two 160-col passes, K=32
    #pragma unroll
    for (int p = 0; p < 2; p++) {
        const int nb = p * NH2 + ng * 40;
        #pragma unroll
        for (int kk = 0; kk < 2; kk++) {
            uint32_t a[2][4];
            #pragma unroll
            for (int m = 0; m < 2; m++)
                ldsm_x4(a[m], zms_a + ((r0 + m * 16 + a_ro) * ZS + kk * 16 + a_cb) * 2);
            #pragma unroll
            for (int tp = 0; tp < 2; tp++) {
                uint32_t b[4];
                ldsm_x4t(b, w1s_a + ((kk * 16 + b_k) * RS + nb + tp * 16 + b_nb) * 2);
                #pragma unroll
                for (int m = 0; m < 2; m++) {
                    mma16(acc[m][2 * tp],     a[m], b[0], b[1]);
                    mma16(acc[m][2 * tp + 1], a[m], b[2], b[3]);
                }
            }
            uint32_t bx[2];
            ldsm_x2t(bx, w1s_a + ((kk * 16 + b_k2) * RS + nb + 32) * 2);
            #pragma unroll
            for (int m = 0; m < 2; m++)
                mma16(acc[m][4], a[m], bx[0], bx[1]);
        }
        // relu + pack -> G1s cols [nb, nb+40), rezero acc
        #pragma unroll
        for (int m = 0; m < 2; m++) {
            int row = r0 + m * 16 + (lane >> 2);
            #pragma unroll
            for (int t = 0; t < 5; t++) {
                int c = nb + t * 8 + 2 * (lane & 3);
                __half2 lo = __floats2half2_rn(fmaxf(acc[m][t][0], 0.f), fmaxf(acc[m][t][1], 0.f));
                __half2 hi = __floats2half2_rn(fmaxf(acc[m][t][2], 0.f), fmaxf(acc[m][t][3], 0.f));
                *(__half2*)(G1s + row * RS + c)       = lo;
                *(__half2*)(G1s + (row + 8) * RS + c) = hi;
                acc[m][t][0] = acc[m][t][1] = acc[m][t][2] = acc[m][t][3] = 0.f;
            }
        }
    }
    __syncthreads();   // G1 visible to all warps

    // ---- gemm2 mainloop: 10 pair-iterations, 3-slot ring, prefetch dist 1
    for (int ip = 0; ip < NPAIR; ip++) {
        if (ip + 1 < NPAIR) {
            const __half* src = w2base + (ip + 1) * 2 * HCH_H;
            uint32_t dst = ring_a + ((ip + 1) % 3) * HPAIR_B;
            for (int u = tid; u < HPAIR_U; u += 256)
                cp16(dst + u * 16, src + u * 8);
        }
        cp_commit();
        asm volatile("cp.async.wait_group 1;");
        __syncthreads();

        const uint32_t pbase = ring_a + (ip % 3) * HPAIR_B;
        #pragma unroll
        for (int q = 0; q < 2; q++) {
            const int kc = 2 * ip + q;
            if (kc < 19) {
                const uint32_t Bs = pbase + q * HCH_B;
                uint32_t a[2][4];
                #pragma unroll
                for (int m = 0; m < 2; m++)
                    ldsm_x4(a[m], g1s_a + ((r0 + m * 16 + a_ro) * RS + kc * 16 + a_cb) * 2);
                #pragma unroll
                for (int tp = 0; tp < 2; tp++) {
                    uint32_t b[4];
                    ldsm_x4t(b, Bs + (b_k * HRS + ng * 40 + tp * 16 + b_nb) * 2);
                    #pragma unroll
                    for (int m = 0; m < 2; m++) {
                        mma16(acc[m][2 * tp],     a[m], b[0], b[1]);
                        mma16(acc[m][2 * tp + 1], a[m], b[2], b[3]);
                    }
                }
                uint32_t bx[2];
                ldsm_x2t(bx, Bs + (b_k2 * HRS + ng * 40 + 32) * 2);
                #pragma unroll
                for (int m = 0; m < 2; m++)
                    mma16(acc[m][4], a[m], bx[0], bx[1]);
            }
        }
    }

    // ---- epilogue: rs = sum over this warp's cols of relu(acc + b2) * cw
    #pragma unroll
    for (int m = 0; m < 2; m++) {
        float rs0 = 0.f, rs1 = 0.f;
        #pragma unroll
        for (int t = 0; t < 5; t++) {
            int cb = ng * 40 + t * 8 + 2 * (lane & 3);
            #pragma unroll
            for (int q = 0; q < 2; q++) {
                int c = cb + q;
                rs0 += fmaxf(acc[m][t][q] + b2s[c], 0.f) * cws[c];
                rs1 += fmaxf(acc[m][t][2 + q] + b2s[c], 0.f) * cws[c];
            }
        }
        rs0 += __shfl_xor_sync(0xffffffffu, rs0, 1);
        rs0 += __shfl_xor_sync(0xffffffffu, rs0, 2);
        rs1 += __shfl_xor_sync(0xffffffffu, rs1, 1);
        rs1 += __shfl_xor_sync(0xffffffffu, rs1, 2);
        if ((lane & 3) == 0) {
            int rbase = r0 + m * 16 + (lane >> 2);
            atomicAdd(&outs[rbase], rs0);
            atomicAdd(&outs[rbase + 8], rs1);
        }
    }
    __syncthreads();
    if (tid < MT2)
        atomicAdd(&xmean[(b0 + tid) * DD + j], outs[tid]);
}

// ---------------------------------------------------------------------------
// Launch
// ---------------------------------------------------------------------------
extern "C" void kernel_launch(void* const* d_in, const int* in_sizes, int n_in,
                              void* d_out, int out_size) {
    const float* x      = (const float*)d_in[0];
    const float* eps    = (const float*)d_in[1];
    const float* Wmask  = (const float*)d_in[2];
    const float* qz_w1  = (const float*)d_in[3];
    const float* qz_b1  = (const float*)d_in[4];
    const float* qz_w2  = (const float*)d_in[5];
    const float* qz_b2  = (const float*)d_in[6];
    const float* zm_w   = (const float*)d_in[7];
    const float* zm_b   = (const float*)d_in[8];
    const float* zl_w   = (const float*)d_in[9];
    const float* zl_b   = (const float*)d_in[10];
    const float* gen_w1 = (const float*)d_in[11];
    const float* gen_w2 = (const float*)d_in[12];
    const float* gen_b2 = (const float*)d_in[13];
    const float* col_w  = (const float*)d_in[14];
    const float* col_b  = (const float*)d_in[15];

    float* out    = (float*)d_out;
    float* xmean  = out;
    float* z_out  = out + BB * DD;
    float* zm_out = z_out + BB * LL;
    float* zl_out = zm_out + BB * LL;

    // Pack fp16 images
    {
        int total = 680192;
        pack_weights<<<(total + 255) / 256, 256>>>(gen_w1, gen_w2, qz_w1,
                                                   qz_w2, zm_w, zl_w, x);
    }
    // xmean init (col_b broadcast)
    xinit_kernel<<<(BB * DD + 255) / 256, 256>>>(col_b, xmean);
    // enc1
    {
        cudaFuncSetAttribute(enc1_kernel,
                             cudaFuncAttributeMaxDynamicSharedMemorySize,
                             E1_SMEM);
        dim3 grid(8, 5);
        enc1_kernel<<<grid, 256, E1_SMEM>>>(qz_b1);
    }
    // enc2 + heads fused
    {
        cudaFuncSetAttribute(enc2_heads_kernel,
                             cudaFuncAttributeMaxDynamicSharedMemorySize,
                             E2_SMEM);
        enc2_heads_kernel<<<BB / 64, 512, E2_SMEM>>>(eps, qz_b2, zm_b, zl_b,
                                                     z_out, zm_out, zl_out);
    }
    // split decoder: 8 batch-tiles x 512 columns x 2 n-halves
    {
        cudaFuncSetAttribute(decoder_kernel,
                             cudaFuncAttributeMaxDynamicSharedMemorySize,
                             D_SMEM);
        dim3 grid(BB / MT2, DD, 2);
        decoder_kernel<<<grid, 256, D_SMEM>>>(Wmask, gen_b2, col_w, xmean);
    }
}

// round 14
// speedup vs baseline: 1.3556x; 1.3556x over previous
#include <cuda_runtime.h>
#include <cuda_fp16.h>
#include <cuda_bf16.h>
#include <math.h>
#include <stdint.h>

// Problem constants
#define BB 512
#define DD 512
#define LL 32
#define HH 300
#define MT 128
#define NP 320
#define RS 328
#define ZS 40
#define NPAIR 10            // enc2 pair iterations
#define CHUNK_H (16 * RS)   // 5248 halves
#define CHUNK_B (CHUNK_H * 2)
#define CHUNK_U (CHUNK_B / 16)
#define PAIR_B  (2 * CHUNK_B)
#define W1_U    (2 * CHUNK_U)

// Decoder: 5-chunk sections {5,5,5,4}, 2-slot ring
#define SEC 5
#define SEC_B (SEC * CHUNK_B)              // 52480
#define SO_ZM   0                          // 128*40*2  = 10240
#define SO_G1   10240                      // 128*328*2 = 83968 -> 94208
#define SO_W1   94208                      // 32*328*2  = 20992 -> 115200
#define SO_RING 115200                     // 2*52480   = 104960 -> 220160
#define SO_B2   220160                     // 1280
#define SO_CW   221440                     // 1280
#define SO_OUT  222720                     // 512
#define SMEM_TOTAL 223232

// enc1 SMEM layout
#define XRS 520
#define SRS 72
#define SCH_B 2304
#define SCH_U 144
#define SPAIR_B 4608
#define SPAIR_U 288
#define E1_XS   0
#define E1_RING 66560
#define E1_B1   84992
#define E1_SMEM 85248

// enc2 SMEM layout
#define E2_H1   0
#define E2_H2   41984
#define E2_RING 83968
#define E2_ZW   167936
#define E2_B2   214016
#define E2_ZB   215296
#define E2_SMEM 215808
#define ZWS 72

// ---------------------------------------------------------------------------
// Scratch (device globals: allocation-free rule)
// ---------------------------------------------------------------------------
__device__ float  g_z[BB * LL];
__device__ __half g_w1h[LL * RS];            // decoder W1
__device__ __half g_w2h[19 * CHUNK_H];       // decoder W2 (19 chunks)
__device__ __half g_ew1[32 * CHUNK_H];       // qz_w1 (32 chunks)
__device__ __half g_ew2[20 * CHUNK_H];       // qz_w2 (20 chunks, last zero)
__device__ __half g_zw[NP * ZWS];            // zm|zl
__device__ __half g_xh[BB * XRS];            // x fp16 padded
__device__ __half g_h1h[BB * RS];            // h1 fp16

// ---------------------------------------------------------------------------
// PTX helpers
// ---------------------------------------------------------------------------
__device__ __forceinline__ void ldsm_x4(uint32_t* r, uint32_t addr) {
    asm volatile("ldmatrix.sync.aligned.m8n8.x4.shared.b16 {%0,%1,%2,%3}, [%4];"
                 : "=r"(r[0]), "=r"(r[1]), "=r"(r[2]), "=r"(r[3]) : "r"(addr));
}
__device__ __forceinline__ void ldsm_x4t(uint32_t* r, uint32_t addr) {
    asm volatile("ldmatrix.sync.aligned.m8n8.x4.trans.shared.b16 {%0,%1,%2,%3}, [%4];"
                 : "=r"(r[0]), "=r"(r[1]), "=r"(r[2]), "=r"(r[3]) : "r"(addr));
}
__device__ __forceinline__ void mma16(float* d, const uint32_t* a, uint32_t b0, uint32_t b1) {
    asm volatile(
        "mma.sync.aligned.m16n8k16.row.col.f32.f16.f16.f32 "
        "{%0,%1,%2,%3}, {%4,%5,%6,%7}, {%8,%9}, {%0,%1,%2,%3};"
        : "+f"(d[0]), "+f"(d[1]), "+f"(d[2]), "+f"(d[3])
        : "r"(a[0]), "r"(a[1]), "r"(a[2]), "r"(a[3]), "r"(b0), "r"(b1));
}
__device__ __forceinline__ void cp16(uint32_t dst, const void* src) {
    asm volatile("cp.async.cg.shared.global [%0], [%1], 16;" :: "r"(dst), "l"(src));
}
__device__ __forceinline__ void cp_commit() {
    asm volatile("cp.async.commit_group;");
}

// ---------------------------------------------------------------------------
// Pack fp16 images
// ---------------------------------------------------------------------------
__global__ void pack_weights(const float* __restrict__ gen_w1,
                             const float* __restrict__ gen_w2,
                             const float* __restrict__ qz_w1,
                             const float* __restrict__ qz_w2,
                             const float* __restrict__ zm_w,
                             const float* __restrict__ zl_w,
                             const float* __restrict__ x) {
    int idx = blockIdx.x * blockDim.x + threadIdx.x;
    const int S0 = LL * RS;                 // 10496
    const int S1 = S0 + 19 * CHUNK_H;       // 110208
    const int S2 = S1 + 32 * CHUNK_H;       // 278144
    const int S3 = S2 + 20 * CHUNK_H;       // 383104
    const int S4 = S3 + NP * ZWS;           // 406144
    const int S5 = S4 + BB * XRS;           // 672384
    if (idx < S0) {
        int r = idx / RS, c = idx % RS;
        g_w1h[idx] = (c < HH) ? __float2half(gen_w1[r * HH + c]) : __half(0.f);
    } else if (idx < S1) {
        int i = idx - S0;
        int k = i / RS, c = i % RS;
        g_w2h[i] = (k < HH && c < HH) ? __float2half(gen_w2[k * HH + c]) : __half(0.f);
    } else if (idx < S2) {
        int i = idx - S1;
        int k = i / RS, c = i % RS;
        g_ew1[i] = (c < HH) ? __float2half(qz_w1[k * HH + c]) : __half(0.f);
    } else if (idx < S3) {
        int i = idx - S2;
        int k = i / RS, c = i % RS;
        g_ew2[i] = (k < HH && c < HH) ? __float2half(qz_w2[k * HH + c]) : __half(0.f);
    } else if (idx < S4) {
        int i = idx - S3;
        int k = i / ZWS, c = i % ZWS;
        float v = 0.f;
        if (k < HH) {
            if (c < 32) v = zm_w[k * LL + c];
            else if (c < 64) v = zl_w[k * LL + (c - 32)];
        }
        g_zw[i] = __float2half(v);
    } else if (idx < S5) {
        int i = idx - S4;
        int r = i / XRS, c = i % XRS;
        g_xh[i] = (c < DD) ? __float2half(x[r * DD + c]) : __half(0.f);
    }
}

// ---------------------------------------------------------------------------
// enc1: h1 = relu(x @ qz_w1 + b1). Grid (8, 5). (unchanged)
// ---------------------------------------------------------------------------
__global__ void __launch_bounds__(256, 2)
enc1_kernel(const float* __restrict__ qz_b1) {
    extern __shared__ char smc[];
    float* b1s = (float*)(smc + E1_B1);
    const uint32_t xs_a   = (uint32_t)__cvta_generic_to_shared(smc + E1_XS);
    const uint32_t ring_a = (uint32_t)__cvta_generic_to_shared(smc + E1_RING);

    const int tid  = threadIdx.x;
    const int lane = tid & 31;
    const int warp = tid >> 5;
    const int ms   = (warp & 3) * 16;
    const int nq   = warp >> 2;
    const int m0   = blockIdx.x * 64;
    const int nc0  = blockIdx.y * 64;
    const int seg  = lane >> 3, rr = lane & 7;

    {
        const __half* src = g_xh + m0 * XRS;
        for (int u = tid; u < 64 * XRS / 8; u += 256)
            cp16(xs_a + u * 16, src + u * 8);
        cp_commit();
        #pragma unroll
        for (int p = 0; p < 2; p++) {
            for (int u = tid; u < SPAIR_U; u += 256) {
                int ch = u / SCH_U, uu = u % SCH_U;
                int row = uu / 9, c16 = uu % 9;
                const __half* s = g_ew1 + ((p * 2 + ch) * 16 + row) * RS + nc0 + c16 * 8;
                cp16(ring_a + p * SPAIR_B + ch * SCH_B + (row * SRS + c16 * 8) * 2, s);
            }
            cp_commit();
        }
    }
    if (tid < 64) {
        int g = nc0 + tid;
        b1s[tid] = (g < HH) ? qz_b1[g] : 0.f;
    }
    asm volatile("cp.async.wait_group 2;");
    __syncthreads();

    const int a_ro = (seg & 1) * 8 + rr;
    const int a_cb = (seg >> 1) * 8;
    const int b_k  = (seg & 1) * 8 + rr;
    const int b_nb = (seg >> 1) * 8;

    float acc[4][4];
    #pragma unroll
    for (int t = 0; t < 4; t++)
        #pragma unroll
        for (int i = 0; i < 4; i++) acc[t][i] = 0.f;

    for (int ip = 0; ip < 16; ip++) {
        if (ip + 2 < 16) {
            for (int u = tid; u < SPAIR_U; u += 256) {
                int ch = u / SCH_U, uu = u % SCH_U;
                int row = uu / 9, c16 = uu % 9;
                const __half* s = g_ew1 + (((ip + 2) * 2 + ch) * 16 + row) * RS + nc0 + c16 * 8;
                cp16(ring_a + ((ip + 2) & 3) * SPAIR_B + ch * SCH_B + (row * SRS + c16 * 8) * 2, s);
            }
        }
        cp_commit();
        asm volatile("cp.async.wait_group 2;");
        __syncthreads();

        const uint32_t pbase = ring_a + (ip & 3) * SPAIR_B;
        #pragma unroll
        for (int q = 0; q < 2; q++) {
            const int kc = 2 * ip + q;
            uint32_t a[4];
            ldsm_x4(a, xs_a + ((ms + a_ro) * XRS + kc * 16 + a_cb) * 2);
            const uint32_t Bs = pbase + q * SCH_B;
            #pragma unroll
            for (int p2 = 0; p2 < 2; p2++) {
                int n0 = (nq * 4 + 2 * p2) * 8;
                uint32_t b[4];
                ldsm_x4t(b, Bs + (b_k * SRS + n0 + b_nb) * 2);
                mma16(acc[2 * p2],     a, b[0], b[1]);
                mma16(acc[2 * p2 + 1], a, b[2], b[3]);
            }
        }
    }

    {
        int row = ms + (lane >> 2);
        #pragma unroll
        for (int t = 0; t < 4; t++) {
            int cl = (nq * 4 + t) * 8 + 2 * (lane & 3);
            float v0 = fmaxf(acc[t][0] + b1s[cl], 0.f);
            float v1 = fmaxf(acc[t][1] + b1s[cl + 1], 0.f);
            float v2 = fmaxf(acc[t][2] + b1s[cl], 0.f);
            float v3 = fmaxf(acc[t][3] + b1s[cl + 1], 0.f);
            *(__half2*)(g_h1h + (m0 + row) * RS + nc0 + cl)     = __floats2half2_rn(v0, v1);
            *(__half2*)(g_h1h + (m0 + row + 8) * RS + nc0 + cl) = __floats2half2_rn(v2, v3);
        }
    }
}

// ---------------------------------------------------------------------------
// enc2 + heads fused (unchanged)
// ---------------------------------------------------------------------------
__global__ void __launch_bounds__(512, 1)
enc2_heads_kernel(const float* __restrict__ eps,
                  const float* __restrict__ qz_b2,
                  const float* __restrict__ zm_b,
                  const float* __restrict__ zl_b,
                  float* __restrict__ z_out,
                  float* __restrict__ zm_out,
                  float* __restrict__ zl_out) {
    extern __shared__ char smc[];
    float* b2s = (float*)(smc + E2_B2);
    float* zbb = (float*)(smc + E2_ZB);
    float* zbuf = (float*)(smc + E2_RING);
    const uint32_t h1_a   = (uint32_t)__cvta_generic_to_shared(smc + E2_H1);
    const uint32_t h2_a   = (uint32_t)__cvta_generic_to_shared(smc + E2_H2);
    const uint32_t ring_a = (uint32_t)__cvta_generic_to_shared(smc + E2_RING);
    const uint32_t zw_a   = (uint32_t)__cvta_generic_to_shared(smc + E2_ZW);
    __half* h2s = (__half*)(smc + E2_H2);

    const int tid  = threadIdx.x;
    const int lane = tid & 31;
    const int warp = tid >> 5;
    const int ms   = (warp & 3) * 16;
    const int nq   = warp >> 2;
    const int m0   = blockIdx.x * 64;
    const int seg  = lane >> 3, rr = lane & 7;

    {
        const __half* h1src = g_h1h + m0 * RS;
        for (int u = tid; u < 64 * RS / 8; u += 512)
            cp16(h1_a + u * 16, h1src + u * 8);
        cp_commit();
        for (int u = tid; u < NP * ZWS / 8; u += 512)
            cp16(zw_a + u * 16, g_zw + u * 8);
        cp_commit();
        #pragma unroll
        for (int p = 0; p < 2; p++) {
            const __half* src = g_ew2 + p * 2 * CHUNK_H;
            for (int u = tid; u < 2 * CHUNK_U; u += 512)
                cp16(ring_a + p * PAIR_B + u * 16, src + u * 8);
            cp_commit();
        }
    }
    for (int c = tid; c < NP; c += 512)
        b2s[c] = (c < HH) ? qz_b2[c] : 0.f;
    if (tid < 32) zbb[tid] = zm_b[tid];
    else if (tid < 64) zbb[64 + tid - 32] = zl_b[tid - 32];

    asm volatile("cp.async.wait_group 2;");
    __syncthreads();

    const int a_ro = (seg & 1) * 8 + rr;
    const int a_cb = (seg >> 1) * 8;
    const int b_k  = (seg & 1) * 8 + rr;
    const int b_nb = (seg >> 1) * 8;

    float acc[10][4];
    #pragma unroll
    for (int t = 0; t < 10; t++)
        #pragma unroll
        for (int i = 0; i < 4; i++) acc[t][i] = 0.f;

    for (int ip = 0; ip < NPAIR; ip++) {
        if (ip + 2 < NPAIR) {
            const __half* src = g_ew2 + (ip + 2) * 2 * CHUNK_H;
            uint32_t dst = ring_a + ((ip + 2) & 3) * PAIR_B;
            for (int u = tid; u < 2 * CHUNK_U; u += 512)
                cp16(dst + u * 16, src + u * 8);
        }
        cp_commit();
        asm volatile("cp.async.wait_group 2;");
        __syncthreads();

        const uint32_t pbase = ring_a + (ip & 3) * PAIR_B;
        #pragma unroll
        for (int q = 0; q < 2; q++) {
            const int kc = 2 * ip + q;
            if (kc < 19) {
                const uint32_t Bs = pbase + q * CHUNK_B;
                uint32_t a[4];
                ldsm_x4(a, h1_a + ((ms + a_ro) * RS + kc * 16 + a_cb) * 2);
                #pragma unroll
                for (int p = 0; p < 5; p++) {
                    int n0 = (nq * 10 + 2 * p) * 8;
                    uint32_t b[4];
                    ldsm_x4t(b, Bs + (b_k * RS + n0 + b_nb) * 2);
                    mma16(acc[2 * p],     a, b[0], b[1]);
                    mma16(acc[2 * p + 1], a, b[2], b[3]);
                }
            }
        }
    }

    {
        int row = ms + (lane >> 2);
        #pragma unroll
        for (int t = 0; t < 10; t++) {
            int c = (nq * 10 + t) * 8 + 2 * (lane & 3);
            float v0 = fmaxf(acc[t][0] + b2s[c], 0.f);
            float v1 = fmaxf(acc[t][1] + b2s[c + 1], 0.f);
            float v2 = fmaxf(acc[t][2] + b2s[c], 0.f);
            float v3 = fmaxf(acc[t][3] + b2s[c + 1], 0.f);
            *(__half2*)(h2s + row * RS + c)       = __floats2half2_rn(v0, v1);
            *(__half2*)(h2s + (row + 8) * RS + c) = __floats2half2_rn(v2, v3);
        }
    }
    __syncthreads();

    float ah[2][4];
    #pragma unroll
    for (int t = 0; t < 2; t++)
        #pragma unroll
        for (int i = 0; i < 4; i++) ah[t][i] = 0.f;
    for (int ks = 0; ks < 19; ks++) {
        uint32_t a[4];
        ldsm_x4(a, h2_a + ((ms + a_ro) * RS + ks * 16 + a_cb) * 2);
        int n0 = nq * 16;
        uint32_t b[4];
        ldsm_x4t(b, zw_a + ((ks * 16 + b_k) * ZWS + n0 + b_nb) * 2);
        mma16(ah[0], a, b[0], b[1]);
        mma16(ah[1], a, b[2], b[3]);
    }
    __syncthreads();

    {
        int row = ms + (lane >> 2);
        #pragma unroll
        for (int t = 0; t < 2; t++) {
            int c = nq * 16 + t * 8 + 2 * (lane & 3);
            zbuf[row * 68 + c]           = ah[t][0];
            zbuf[row * 68 + c + 1]       = ah[t][1];
            zbuf[(row + 8) * 68 + c]     = ah[t][2];
            zbuf[(row + 8) * 68 + c + 1] = ah[t][3];
        }
    }
    __syncthreads();

    for (int i = tid; i < 64 * LL; i += 512) {
        int r = i >> 5, l = i & 31;
        float zm = zbuf[r * 68 + l] + zbb[l];
        float zl = zbuf[r * 68 + 32 + l] + zbb[64 + l];
        int o = (m0 + r) * LL + l;
        float zv = zm + eps[o] * expf(0.5f * zl);
        zm_out[o] = zm;
        zl_out[o] = zl;
        z_out[o]  = zv;
        g_z[o]    = zv;
    }
}

// ---------------------------------------------------------------------------
// Decoder: 5-chunk sections {5,5,5,4}, 2-slot ring. CTA = (j, 128 rows).
// Per section: wait(ready) -> sync (slot vacated) -> issue next -> consume.
// ---------------------------------------------------------------------------
#define CHUNK_MMA(kc, Bs)                                                     \
    {                                                                         \
        uint32_t a[2][4];                                                     \
        _Pragma("unroll")                                                     \
        for (int m = 0; m < 2; m++)                                           \
            ldsm_x4(a[m], g1s_a + ((r0 + m * 16 + a_ro) * RS + (kc) * 16 + a_cb) * 2); \
        _Pragma("unroll")                                                     \
        for (int p = 0; p < 5; p++) {                                         \
            int n0 = (nq * 10 + 2 * p) * 8;                                   \
            uint32_t b[4];                                                    \
            ldsm_x4t(b, (Bs) + (b_k * RS + n0 + b_nb) * 2);                   \
            _Pragma("unroll")                                                 \
            for (int m = 0; m < 2; m++) {                                     \
                mma16(acc[m][2 * p],     a[m], b[0], b[1]);                   \
                mma16(acc[m][2 * p + 1], a[m], b[2], b[3]);                   \
            }                                                                 \
        }                                                                     \
    }

__global__ void __launch_bounds__(512, 1)
decoder_kernel(const float* __restrict__ Wmask,
               const float* __restrict__ gen_b2,
               const float* __restrict__ col_w,
               const float* __restrict__ col_b,
               float* __restrict__ xmean) {
    extern __shared__ char smc[];
    __half* Zms  = (__half*)(smc + SO_ZM);
    __half* G1s  = (__half*)(smc + SO_G1);
    float*  b2s  = (float*)(smc + SO_B2);
    float*  cws  = (float*)(smc + SO_CW);
    float*  outs = (float*)(smc + SO_OUT);

    const int tid  = threadIdx.x;
    const int lane = tid & 31;
    const int warp = tid >> 5;
    const int r0   = (warp & 3) * 32;
    const int nq   = warp >> 2;
    const int j    = blockIdx.y;
    const int b0   = blockIdx.x * MT;
    const int seg  = lane >> 3, rr = lane & 7;

    const uint32_t zms_a  = (uint32_t)__cvta_generic_to_shared(smc + SO_ZM);
    const uint32_t g1s_a  = (uint32_t)__cvta_generic_to_shared(smc + SO_G1);
    const uint32_t w1s_a  = (uint32_t)__cvta_generic_to_shared(smc + SO_W1);
    const uint32_t ring_a = (uint32_t)__cvta_generic_to_shared(smc + SO_RING);

    // prologue: W1 (group), section 0 = chunks 0..4 (group)
    {
        for (int u = tid; u < W1_U; u += 512)
            cp16(w1s_a + u * 16, g_w1h + u * 8);
        cp_commit();
        for (int u = tid; u < SEC * CHUNK_U; u += 512)
            cp16(ring_a + u * 16, g_w2h + u * 8);
        cp_commit();
    }

    for (int idx = tid; idx < MT * LL; idx += 512) {
        int bl = idx >> 5, l = idx & 31;
        float v = g_z[(b0 + bl) * LL + l] * __ldg(Wmask + j * LL + l);
        Zms[bl * ZS + l] = __float2half(v);
    }
    for (int c = tid; c < NP; c += 512) {
        b2s[c] = (c < HH) ? __ldg(gen_b2 + c) : 0.f;
        cws[c] = (c < HH) ? __ldg(col_w + j * HH + c) : 0.f;
    }
    if (tid < MT) outs[tid] = 0.f;

    asm volatile("cp.async.wait_group 1;");   // W1 landed
    __syncthreads();

    const int a_ro = (seg & 1) * 8 + rr;
    const int a_cb = (seg >> 1) * 8;
    const int b_k  = (seg & 1) * 8 + rr;
    const int b_nb = (seg >> 1) * 8;

    float acc[2][10][4];
    #pragma unroll
    for (int m = 0; m < 2; m++)
        #pragma unroll
        for (int t = 0; t < 10; t++)
            #pragma unroll
            for (int i = 0; i < 4; i++) acc[m][t][i] = 0.f;

    // gemm1: G1 = relu(Zm @ W1)
    #pragma unroll
    for (int kk = 0; kk < 2; kk++) {
        uint32_t a[2][4];
        #pragma unroll
        for (int m = 0; m < 2; m++)
            ldsm_x4(a[m], zms_a + ((r0 + m * 16 + a_ro) * ZS + kk * 16 + a_cb) * 2);
        #pragma unroll
        for (int p = 0; p < 5; p++) {
            int n0 = (nq * 10 + 2 * p) * 8;
            uint32_t b[4];
            ldsm_x4t(b, w1s_a + ((kk * 16 + b_k) * RS + n0 + b_nb) * 2);
            #pragma unroll
            for (int m = 0; m < 2; m++) {
                mma16(acc[m][2 * p],     a[m], b[0], b[1]);
                mma16(acc[m][2 * p + 1], a[m], b[2], b[3]);
            }
        }
    }
    {
        #pragma unroll
        for (int m = 0; m < 2; m++) {
            int row = r0 + m * 16 + (lane >> 2);
            #pragma unroll
            for (int t = 0; t < 10; t++) {
                int c = (nq * 10 + t) * 8 + 2 * (lane & 3);
                __half2 lo = __floats2half2_rn(fmaxf(acc[m][t][0], 0.f), fmaxf(acc[m][t][1], 0.f));
                __half2 hi = __floats2half2_rn(fmaxf(acc[m][t][2], 0.f), fmaxf(acc[m][t][3], 0.f));
                *(__half2*)(G1s + row * RS + c)       = lo;
                *(__half2*)(G1s + (row + 8) * RS + c) = hi;
                acc[m][t][0] = acc[m][t][1] = acc[m][t][2] = acc[m][t][3] = 0.f;
            }
        }
    }
    __syncthreads();    // G1s visible

    // mainloop: 4 sections {5,5,5,4}
    for (int ip = 0; ip < 4; ip++) {
        asm volatile("cp.async.wait_group 0;");   // section ip resident
        __syncthreads();                          // prior slot fully consumed

        if (ip < 3) {
            const int base = SEC * (ip + 1);
            const int cnt  = (19 - base < SEC) ? (19 - base) : SEC;
            const __half* src = g_w2h + base * CHUNK_H;
            uint32_t dst = ring_a + ((ip + 1) & 1) * SEC_B;
            const int units = cnt * CHUNK_U;
            for (int u = tid; u < units; u += 512)
                cp16(dst + u * 16, src + u * 8);
        }
        cp_commit();

        const uint32_t sb = ring_a + (ip & 1) * SEC_B;
        const int cnt = (19 - SEC * ip < SEC) ? (19 - SEC * ip) : SEC;
        #pragma unroll
        for (int q = 0; q < SEC; q++) {
            if (q < cnt) {
                CHUNK_MMA(SEC * ip + q, sb + q * CHUNK_B);
            }
        }
    }

    // epilogue
    #pragma unroll
    for (int m = 0; m < 2; m++) {
        float rs0 = 0.f, rs1 = 0.f;
        #pragma unroll
        for (int t = 0; t < 10; t++) {
            int cb = (nq * 10 + t) * 8 + 2 * (lane & 3);
            #pragma unroll
            for (int q = 0; q < 2; q++) {
                int c = cb + q;
                rs0 += fmaxf(acc[m][t][q] + b2s[c], 0.f) * cws[c];
                rs1 += fmaxf(acc[m][t][2 + q] + b2s[c], 0.f) * cws[c];
            }
        }
        rs0 += __shfl_xor_sync(0xffffffffu, rs0, 1);
        rs0 += __shfl_xor_sync(0xffffffffu, rs0, 2);
        rs1 += __shfl_xor_sync(0xffffffffu, rs1, 1);
        rs1 += __shfl_xor_sync(0xffffffffu, rs1, 2);
        if ((lane & 3) == 0) {
            int rbase = r0 + m * 16 + (lane >> 2);
            atomicAdd(&outs[rbase], rs0);
            atomicAdd(&outs[rbase + 8], rs1);
        }
    }
    __syncthreads();
    if (tid < MT) {
        xmean[(b0 + tid) * DD + j] = outs[tid] + __ldg(col_b + j);
    }
}

// ---------------------------------------------------------------------------
// Launch
// ---------------------------------------------------------------------------
extern "C" void kernel_launch(void* const* d_in, const int* in_sizes, int n_in,
                              void* d_out, int out_size) {
    const float* x      = (const float*)d_in[0];
    const float* eps    = (const float*)d_in[1];
    const float* Wmask  = (const float*)d_in[2];
    const float* qz_w1  = (const float*)d_in[3];
    const float* qz_b1  = (const float*)d_in[4];
    const float* qz_w2  = (const float*)d_in[5];
    const float* qz_b2  = (const float*)d_in[6];
    const float* zm_w   = (const float*)d_in[7];
    const float* zm_b   = (const float*)d_in[8];
    const float* zl_w   = (const float*)d_in[9];
    const float* zl_b   = (const float*)d_in[10];
    const float* gen_w1 = (const float*)d_in[11];
    const float* gen_w2 = (const float*)d_in[12];
    const float* gen_b2 = (const float*)d_in[13];
    const float* col_w  = (const float*)d_in[14];
    const float* col_b  = (const float*)d_in[15];

    float* out    = (float*)d_out;
    float* xmean  = out;
    float* z_out  = out + BB * DD;
    float* zm_out = z_out + BB * LL;
    float* zl_out = zm_out + BB * LL;

    // Pack fp16 images (weights + x)
    {
        int total = LL * RS + (19 + 32 + 20) * CHUNK_H + NP * ZWS + BB * XRS;
        pack_weights<<<(total + 255) / 256, 256>>>(gen_w1, gen_w2, qz_w1,
                                                   qz_w2, zm_w, zl_w, x);
    }
    // enc1
    {
        cudaFuncSetAttribute(enc1_kernel,
                             cudaFuncAttributeMaxDynamicSharedMemorySize,
                             E1_SMEM);
        dim3 grid(8, 5);
        enc1_kernel<<<grid, 256, E1_SMEM>>>(qz_b1);
    }
    // enc2 + heads fused
    {
        cudaFuncSetAttribute(enc2_heads_kernel,
                             cudaFuncAttributeMaxDynamicSharedMemorySize,
                             E2_SMEM);
        enc2_heads_kernel<<<BB / 64, 512, E2_SMEM>>>(eps, qz_b2, zm_b, zl_b,
                                                     z_out, zm_out, zl_out);
    }
    // decoder
    {
        cudaFuncSetAttribute(decoder_kernel,
                             cudaFuncAttributeMaxDynamicSharedMemorySize,
                             SMEM_TOTAL);
        dim3 grid(BB / MT, DD);
        decoder_kernel<<<grid, 512, SMEM_TOTAL>>>(Wmask, gen_b2, col_w, col_b,
                                                  xmean);
    }
}

// round 15
// speedup vs baseline: 1.3572x; 1.0012x over previous
#include <cuda_runtime.h>
#include <cuda_fp16.h>
#include <cuda_bf16.h>
#include <math.h>
#include <stdint.h>

// Problem constants
#define BB 512
#define DD 512
#define LL 32
#define HH 300
#define MT 128
#define NP 320
#define RS 328
#define ZS 40
#define NPAIR 10            // enc2 pair iterations
#define CHUNK_H (16 * RS)   // enc chunk: 5248 halves
#define CHUNK_B (CHUNK_H * 2)
#define CHUNK_U (CHUNK_B / 16)
#define PAIR_B  (2 * CHUNK_B)

// Decoder: stride-312 W1/W2 images, 3 sections {7,6,6}, 2-slot ring
#define DRS 312
#define DCH_H (16 * DRS)    // 4992 halves
#define DCH_B (DCH_H * 2)   // 9984
#define DCH_U (DCH_B / 16)  // 624
#define DW1_H (LL * DRS)    // 9984 halves
#define DW1_U (DW1_H * 2 / 16) // 1248

#define SO_ZM    0                         // 10240
#define SO_G1    10240                     // 83968 -> 94208
#define SO_SLOT0 94208                     // 7*9984 = 69888 -> 164096
#define SO_SLOT1 164096                    // 6*9984 = 59904 -> 224000  (W1 home)
#define SO_B2    224000                    // 1280
#define SO_CW    225280                    // 1280
#define SO_OUT   226560                    // 512
#define SMEM_TOTAL 227072

// enc1 SMEM layout
#define XRS 520
#define SRS 72
#define SCH_B 2304
#define SCH_U 144
#define SPAIR_B 4608
#define SPAIR_U 288
#define E1_XS   0
#define E1_RING 66560
#define E1_B1   84992
#define E1_SMEM 85248

// enc2 SMEM layout
#define E2_H1   0
#define E2_H2   41984
#define E2_RING 83968
#define E2_ZW   167936
#define E2_B2   214016
#define E2_ZB   215296
#define E2_SMEM 215808
#define ZWS 72

// ---------------------------------------------------------------------------
// Scratch (device globals: allocation-free rule)
// ---------------------------------------------------------------------------
__device__ float  g_z[BB * LL];
__device__ __half g_w1h[DW1_H];              // decoder W1, stride 312
__device__ __half g_w2h[19 * DCH_H];         // decoder W2 (19 chunks, stride 312)
__device__ __half g_ew1[32 * CHUNK_H];       // qz_w1 (32 chunks, stride 328)
__device__ __half g_ew2[20 * CHUNK_H];       // qz_w2 (20 chunks, last zero)
__device__ __half g_zw[NP * ZWS];            // zm|zl
__device__ __half g_xh[BB * XRS];            // x fp16 padded
__device__ __half g_h1h[BB * RS];            // h1 fp16

// ---------------------------------------------------------------------------
// PTX helpers
// ---------------------------------------------------------------------------
__device__ __forceinline__ void ldsm_x4(uint32_t* r, uint32_t addr) {
    asm volatile("ldmatrix.sync.aligned.m8n8.x4.shared.b16 {%0,%1,%2,%3}, [%4];"
                 : "=r"(r[0]), "=r"(r[1]), "=r"(r[2]), "=r"(r[3]) : "r"(addr));
}
__device__ __forceinline__ void ldsm_x4t(uint32_t* r, uint32_t addr) {
    asm volatile("ldmatrix.sync.aligned.m8n8.x4.trans.shared.b16 {%0,%1,%2,%3}, [%4];"
                 : "=r"(r[0]), "=r"(r[1]), "=r"(r[2]), "=r"(r[3]) : "r"(addr));
}
__device__ __forceinline__ void mma16(float* d, const uint32_t* a, uint32_t b0, uint32_t b1) {
    asm volatile(
        "mma.sync.aligned.m16n8k16.row.col.f32.f16.f16.f32 "
        "{%0,%1,%2,%3}, {%4,%5,%6,%7}, {%8,%9}, {%0,%1,%2,%3};"
        : "+f"(d[0]), "+f"(d[1]), "+f"(d[2]), "+f"(d[3])
        : "r"(a[0]), "r"(a[1]), "r"(a[2]), "r"(a[3]), "r"(b0), "r"(b1));
}
__device__ __forceinline__ void cp16(uint32_t dst, const void* src) {
    asm volatile("cp.async.cg.shared.global [%0], [%1], 16;" :: "r"(dst), "l"(src));
}
__device__ __forceinline__ void cp_commit() {
    asm volatile("cp.async.commit_group;");
}

// ---------------------------------------------------------------------------
// Pack fp16 images
// ---------------------------------------------------------------------------
__global__ void pack_weights(const float* __restrict__ gen_w1,
                             const float* __restrict__ gen_w2,
                             const float* __restrict__ qz_w1,
                             const float* __restrict__ qz_w2,
                             const float* __restrict__ zm_w,
                             const float* __restrict__ zl_w,
                             const float* __restrict__ x) {
    int idx = blockIdx.x * blockDim.x + threadIdx.x;
    const int S0 = DW1_H;                   // 9984
    const int S1 = S0 + 19 * DCH_H;         // +94848  = 104832
    const int S2 = S1 + 32 * CHUNK_H;       // +167936 = 272768
    const int S3 = S2 + 20 * CHUNK_H;       // +104960 = 377728
    const int S4 = S3 + NP * ZWS;           // +23040  = 400768
    const int S5 = S4 + BB * XRS;           // +266240 = 667008
    if (idx < S0) {
        int r = idx / DRS, c = idx % DRS;
        g_w1h[idx] = (c < HH) ? __float2half(gen_w1[r * HH + c]) : __half(0.f);
    } else if (idx < S1) {
        int i = idx - S0;
        int k = i / DRS, c = i % DRS;
        g_w2h[i] = (k < HH && c < HH) ? __float2half(gen_w2[k * HH + c]) : __half(0.f);
    } else if (idx < S2) {
        int i = idx - S1;
        int k = i / RS, c = i % RS;
        g_ew1[i] = (c < HH) ? __float2half(qz_w1[k * HH + c]) : __half(0.f);
    } else if (idx < S3) {
        int i = idx - S2;
        int k = i / RS, c = i % RS;
        g_ew2[i] = (k < HH && c < HH) ? __float2half(qz_w2[k * HH + c]) : __half(0.f);
    } else if (idx < S4) {
        int i = idx - S3;
        int k = i / ZWS, c = i % ZWS;
        float v = 0.f;
        if (k < HH) {
            if (c < 32) v = zm_w[k * LL + c];
            else if (c < 64) v = zl_w[k * LL + (c - 32)];
        }
        g_zw[i] = __float2half(v);
    } else if (idx < S5) {
        int i = idx - S4;
        int r = i / XRS, c = i % XRS;
        g_xh[i] = (c < DD) ? __float2half(x[r * DD + c]) : __half(0.f);
    }
}

// ---------------------------------------------------------------------------
// enc1: h1 = relu(x @ qz_w1 + b1). Grid (8, 5). (unchanged)
// ---------------------------------------------------------------------------
__global__ void __launch_bounds__(256, 2)
enc1_kernel(const float* __restrict__ qz_b1) {
    extern __shared__ char smc[];
    float* b1s = (float*)(smc + E1_B1);
    const uint32_t xs_a   = (uint32_t)__cvta_generic_to_shared(smc + E1_XS);
    const uint32_t ring_a = (uint32_t)__cvta_generic_to_shared(smc + E1_RING);

    const int tid  = threadIdx.x;
    const int lane = tid & 31;
    const int warp = tid >> 5;
    const int ms   = (warp & 3) * 16;
    const int nq   = warp >> 2;
    const int m0   = blockIdx.x * 64;
    const int nc0  = blockIdx.y * 64;
    const int seg  = lane >> 3, rr = lane & 7;

    {
        const __half* src = g_xh + m0 * XRS;
        for (int u = tid; u < 64 * XRS / 8; u += 256)
            cp16(xs_a + u * 16, src + u * 8);
        cp_commit();
        #pragma unroll
        for (int p = 0; p < 2; p++) {
            for (int u = tid; u < SPAIR_U; u += 256) {
                int ch = u / SCH_U, uu = u % SCH_U;
                int row = uu / 9, c16 = uu % 9;
                const __half* s = g_ew1 + ((p * 2 + ch) * 16 + row) * RS + nc0 + c16 * 8;
                cp16(ring_a + p * SPAIR_B + ch * SCH_B + (row * SRS + c16 * 8) * 2, s);
            }
            cp_commit();
        }
    }
    if (tid < 64) {
        int g = nc0 + tid;
        b1s[tid] = (g < HH) ? qz_b1[g] : 0.f;
    }
    asm volatile("cp.async.wait_group 2;");
    __syncthreads();

    const int a_ro = (seg & 1) * 8 + rr;
    const int a_cb = (seg >> 1) * 8;
    const int b_k  = (seg & 1) * 8 + rr;
    const int b_nb = (seg >> 1) * 8;

    float acc[4][4];
    #pragma unroll
    for (int t = 0; t < 4; t++)
        #pragma unroll
        for (int i = 0; i < 4; i++) acc[t][i] = 0.f;

    for (int ip = 0; ip < 16; ip++) {
        if (ip + 2 < 16) {
            for (int u = tid; u < SPAIR_U; u += 256) {
                int ch = u / SCH_U, uu = u % SCH_U;
                int row = uu / 9, c16 = uu % 9;
                const __half* s = g_ew1 + (((ip + 2) * 2 + ch) * 16 + row) * RS + nc0 + c16 * 8;
                cp16(ring_a + ((ip + 2) & 3) * SPAIR_B + ch * SCH_B + (row * SRS + c16 * 8) * 2, s);
            }
        }
        cp_commit();
        asm volatile("cp.async.wait_group 2;");
        __syncthreads();

        const uint32_t pbase = ring_a + (ip & 3) * SPAIR_B;
        #pragma unroll
        for (int q = 0; q < 2; q++) {
            const int kc = 2 * ip + q;
            uint32_t a[4];
            ldsm_x4(a, xs_a + ((ms + a_ro) * XRS + kc * 16 + a_cb) * 2);
            const uint32_t Bs = pbase + q * SCH_B;
            #pragma unroll
            for (int p2 = 0; p2 < 2; p2++) {
                int n0 = (nq * 4 + 2 * p2) * 8;
                uint32_t b[4];
                ldsm_x4t(b, Bs + (b_k * SRS + n0 + b_nb) * 2);
                mma16(acc[2 * p2],     a, b[0], b[1]);
                mma16(acc[2 * p2 + 1], a, b[2], b[3]);
            }
        }
    }

    {
        int row = ms + (lane >> 2);
        #pragma unroll
        for (int t = 0; t < 4; t++) {
            int cl = (nq * 4 + t) * 8 + 2 * (lane & 3);
            float v0 = fmaxf(acc[t][0] + b1s[cl], 0.f);
            float v1 = fmaxf(acc[t][1] + b1s[cl + 1], 0.f);
            float v2 = fmaxf(acc[t][2] + b1s[cl], 0.f);
            float v3 = fmaxf(acc[t][3] + b1s[cl + 1], 0.f);
            *(__half2*)(g_h1h + (m0 + row) * RS + nc0 + cl)     = __floats2half2_rn(v0, v1);
            *(__half2*)(g_h1h + (m0 + row + 8) * RS + nc0 + cl) = __floats2half2_rn(v2, v3);
        }
    }
}

// ---------------------------------------------------------------------------
// enc2 + heads fused (unchanged)
// ---------------------------------------------------------------------------
__global__ void __launch_bounds__(512, 1)
enc2_heads_kernel(const float* __restrict__ eps,
                  const float* __restrict__ qz_b2,
                  const float* __restrict__ zm_b,
                  const float* __restrict__ zl_b,
                  float* __restrict__ z_out,
                  float* __restrict__ zm_out,
                  float* __restrict__ zl_out) {
    extern __shared__ char smc[];
    float* b2s = (float*)(smc + E2_B2);
    float* zbb = (float*)(smc + E2_ZB);
    float* zbuf = (float*)(smc + E2_RING);
    const uint32_t h1_a   = (uint32_t)__cvta_generic_to_shared(smc + E2_H1);
    const uint32_t h2_a   = (uint32_t)__cvta_generic_to_shared(smc + E2_H2);
    const uint32_t ring_a = (uint32_t)__cvta_generic_to_shared(smc + E2_RING);
    const uint32_t zw_a   = (uint32_t)__cvta_generic_to_shared(smc + E2_ZW);
    __half* h2s = (__half*)(smc + E2_H2);

    const int tid  = threadIdx.x;
    const int lane = tid & 31;
    const int warp = tid >> 5;
    const int ms   = (warp & 3) * 16;
    const int nq   = warp >> 2;
    const int m0   = blockIdx.x * 64;
    const int seg  = lane >> 3, rr = lane & 7;

    {
        const __half* h1src = g_h1h + m0 * RS;
        for (int u = tid; u < 64 * RS / 8; u += 512)
            cp16(h1_a + u * 16, h1src + u * 8);
        cp_commit();
        for (int u = tid; u < NP * ZWS / 8; u += 512)
            cp16(zw_a + u * 16, g_zw + u * 8);
        cp_commit();
        #pragma unroll
        for (int p = 0; p < 2; p++) {
            const __half* src = g_ew2 + p * 2 * CHUNK_H;
            for (int u = tid; u < 2 * CHUNK_U; u += 512)
                cp16(ring_a + p * PAIR_B + u * 16, src + u * 8);
            cp_commit();
        }
    }
    for (int c = tid; c < NP; c += 512)
        b2s[c] = (c < HH) ? qz_b2[c] : 0.f;
    if (tid < 32) zbb[tid] = zm_b[tid];
    else if (tid < 64) zbb[64 + tid - 32] = zl_b[tid - 32];

    asm volatile("cp.async.wait_group 2;");
    __syncthreads();

    const int a_ro = (seg & 1) * 8 + rr;
    const int a_cb = (seg >> 1) * 8;
    const int b_k  = (seg & 1) * 8 + rr;
    const int b_nb = (seg >> 1) * 8;

    float acc[10][4];
    #pragma unroll
    for (int t = 0; t < 10; t++)
        #pragma unroll
        for (int i = 0; i < 4; i++) acc[t][i] = 0.f;

    for (int ip = 0; ip < NPAIR; ip++) {
        if (ip + 2 < NPAIR) {
            const __half* src = g_ew2 + (ip + 2) * 2 * CHUNK_H;
            uint32_t dst = ring_a + ((ip + 2) & 3) * PAIR_B;
            for (int u = tid; u < 2 * CHUNK_U; u += 512)
                cp16(dst + u * 16, src + u * 8);
        }
        cp_commit();
        asm volatile("cp.async.wait_group 2;");
        __syncthreads();

        const uint32_t pbase = ring_a + (ip & 3) * PAIR_B;
        #pragma unroll
        for (int q = 0; q < 2; q++) {
            const int kc = 2 * ip + q;
            if (kc < 19) {
                const uint32_t Bs = pbase + q * CHUNK_B;
                uint32_t a[4];
                ldsm_x4(a, h1_a + ((ms + a_ro) * RS + kc * 16 + a_cb) * 2);
                #pragma unroll
                for (int p = 0; p < 5; p++) {
                    int n0 = (nq * 10 + 2 * p) * 8;
                    uint32_t b[4];
                    ldsm_x4t(b, Bs + (b_k * RS + n0 + b_nb) * 2);
                    mma16(acc[2 * p],     a, b[0], b[1]);
                    mma16(acc[2 * p + 1], a, b[2], b[3]);
                }
            }
        }
    }

    {
        int row = ms + (lane >> 2);
        #pragma unroll
        for (int t = 0; t < 10; t++) {
            int c = (nq * 10 + t) * 8 + 2 * (lane & 3);
            float v0 = fmaxf(acc[t][0] + b2s[c], 0.f);
            float v1 = fmaxf(acc[t][1] + b2s[c + 1], 0.f);
            float v2 = fmaxf(acc[t][2] + b2s[c], 0.f);
            float v3 = fmaxf(acc[t][3] + b2s[c + 1], 0.f);
            *(__half2*)(h2s + row * RS + c)       = __floats2half2_rn(v0, v1);
            *(__half2*)(h2s + (row + 8) * RS + c) = __floats2half2_rn(v2, v3);
        }
    }
    __syncthreads();

    float ah[2][4];
    #pragma unroll
    for (int t = 0; t < 2; t++)
        #pragma unroll
        for (int i = 0; i < 4; i++) ah[t][i] = 0.f;
    for (int ks = 0; ks < 19; ks++) {
        uint32_t a[4];
        ldsm_x4(a, h2_a + ((ms + a_ro) * RS + ks * 16 + a_cb) * 2);
        int n0 = nq * 16;
        uint32_t b[4];
        ldsm_x4t(b, zw_a + ((ks * 16 + b_k) * ZWS + n0 + b_nb) * 2);
        mma16(ah[0], a, b[0], b[1]);
        mma16(ah[1], a, b[2], b[3]);
    }
    __syncthreads();

    {
        int row = ms + (lane >> 2);
        #pragma unroll
        for (int t = 0; t < 2; t++) {
            int c = nq * 16 + t * 8 + 2 * (lane & 3);
            zbuf[row * 68 + c]           = ah[t][0];
            zbuf[row * 68 + c + 1]       = ah[t][1];
            zbuf[(row + 8) * 68 + c]     = ah[t][2];
            zbuf[(row + 8) * 68 + c + 1] = ah[t][3];
        }
    }
    __syncthreads();

    for (int i = tid; i < 64 * LL; i += 512) {
        int r = i >> 5, l = i & 31;
        float zm = zbuf[r * 68 + l] + zbb[l];
        float zl = zbuf[r * 68 + 32 + l] + zbb[64 + l];
        int o = (m0 + r) * LL + l;
        float zv = zm + eps[o] * expf(0.5f * zl);
        zm_out[o] = zm;
        zl_out[o] = zl;
        z_out[o]  = zv;
        g_z[o]    = zv;
    }
}

// ---------------------------------------------------------------------------
// Decoder: 3 sections {7,6,6}, 2-slot ring, W1 lives in slot1 during gemm1.
// CTA = (j, 128 rows). Per section: wait -> sync -> issue next -> consume.
// ---------------------------------------------------------------------------
#define CHUNK_MMA(kc, Bs)                                                     \
    {                                                                         \
        uint32_t a[2][4];                                                     \
        _Pragma("unroll")                                                     \
        for (int m = 0; m < 2; m++)                                           \
            ldsm_x4(a[m], g1s_a + ((r0 + m * 16 + a_ro) * RS + (kc) * 16 + a_cb) * 2); \
        _Pragma("unroll")                                                     \
        for (int p = 0; p < 5; p++) {                                         \
            int n0 = (nq * 10 + 2 * p) * 8;                                   \
            uint32_t b[4];                                                    \
            ldsm_x4t(b, (Bs) + (b_k * DRS + n0 + b_nb) * 2);                  \
            _Pragma("unroll")                                                 \
            for (int m = 0; m < 2; m++) {                                     \
                mma16(acc[m][2 * p],     a[m], b[0], b[1]);                   \
                mma16(acc[m][2 * p + 1], a[m], b[2], b[3]);                   \
            }                                                                 \
        }                                                                     \
    }

__global__ void __launch_bounds__(512, 1)
decoder_kernel(const float* __restrict__ Wmask,
               const float* __restrict__ gen_b2,
               const float* __restrict__ col_w,
               const float* __restrict__ col_b,
               float* __restrict__ xmean) {
    extern __shared__ char smc[];
    __half* Zms  = (__half*)(smc + SO_ZM);
    __half* G1s  = (__half*)(smc + SO_G1);
    float*  b2s  = (float*)(smc + SO_B2);
    float*  cws  = (float*)(smc + SO_CW);
    float*  outs = (float*)(smc + SO_OUT);

    const int tid  = threadIdx.x;
    const int lane = tid & 31;
    const int warp = tid >> 5;
    const int r0   = (warp & 3) * 32;
    const int nq   = warp >> 2;
    const int j    = blockIdx.y;
    const int b0   = blockIdx.x * MT;
    const int seg  = lane >> 3, rr = lane & 7;

    const uint32_t zms_a  = (uint32_t)__cvta_generic_to_shared(smc + SO_ZM);
    const uint32_t g1s_a  = (uint32_t)__cvta_generic_to_shared(smc + SO_G1);
    const uint32_t slot0  = (uint32_t)__cvta_generic_to_shared(smc + SO_SLOT0);
    const uint32_t slot1  = (uint32_t)__cvta_generic_to_shared(smc + SO_SLOT1);

    // prologue: W1 -> slot1 (group), section 0 = chunks 0..6 -> slot0 (group)
    {
        for (int u = tid; u < DW1_U; u += 512)
            cp16(slot1 + u * 16, g_w1h + u * 8);
        cp_commit();
        for (int u = tid; u < 7 * DCH_U; u += 512)
            cp16(slot0 + u * 16, g_w2h + u * 8);
        cp_commit();
    }

    for (int idx = tid; idx < MT * LL; idx += 512) {
        int bl = idx >> 5, l = idx & 31;
        float v = g_z[(b0 + bl) * LL + l] * __ldg(Wmask + j * LL + l);
        Zms[bl * ZS + l] = __float2half(v);
    }
    for (int c = tid; c < NP; c += 512) {
        b2s[c] = (c < HH) ? __ldg(gen_b2 + c) : 0.f;
        cws[c] = (c < HH) ? __ldg(col_w + j * HH + c) : 0.f;
    }
    if (tid < MT) outs[tid] = 0.f;

    asm volatile("cp.async.wait_group 1;");   // W1 landed
    __syncthreads();

    const int a_ro = (seg & 1) * 8 + rr;
    const int a_cb = (seg >> 1) * 8;
    const int b_k  = (seg & 1) * 8 + rr;
    const int b_nb = (seg >> 1) * 8;

    float acc[2][10][4];
    #pragma unroll
    for (int m = 0; m < 2; m++)
        #pragma unroll
        for (int t = 0; t < 10; t++)
            #pragma unroll
            for (int i = 0; i < 4; i++) acc[m][t][i] = 0.f;

    // gemm1: G1 = relu(Zm @ W1), W1 in slot1 (stride DRS)
    #pragma unroll
    for (int kk = 0; kk < 2; kk++) {
        uint32_t a[2][4];
        #pragma unroll
        for (int m = 0; m < 2; m++)
            ldsm_x4(a[m], zms_a + ((r0 + m * 16 + a_ro) * ZS + kk * 16 + a_cb) * 2);
        #pragma unroll
        for (int p = 0; p < 5; p++) {
            int n0 = (nq * 10 + 2 * p) * 8;
            uint32_t b[4];
            ldsm_x4t(b, slot1 + ((kk * 16 + b_k) * DRS + n0 + b_nb) * 2);
            #pragma unroll
            for (int m = 0; m < 2; m++) {
                mma16(acc[m][2 * p],     a[m], b[0], b[1]);
                mma16(acc[m][2 * p + 1], a[m], b[2], b[3]);
            }
        }
    }
    {
        #pragma unroll
        for (int m = 0; m < 2; m++) {
            int row = r0 + m * 16 + (lane >> 2);
            #pragma unroll
            for (int t = 0; t < 10; t++) {
                int c = (nq * 10 + t) * 8 + 2 * (lane & 3);
                __half2 lo = __floats2half2_rn(fmaxf(acc[m][t][0], 0.f), fmaxf(acc[m][t][1], 0.f));
                __half2 hi = __floats2half2_rn(fmaxf(acc[m][t][2], 0.f), fmaxf(acc[m][t][3], 0.f));
                *(__half2*)(G1s + row * RS + c)       = lo;
                *(__half2*)(G1s + (row + 8) * RS + c) = hi;
                acc[m][t][0] = acc[m][t][1] = acc[m][t][2] = acc[m][t][3] = 0.f;
            }
        }
    }
    __syncthreads();    // G1s visible; W1 (slot1) dead after this point

    // mainloop: 3 sections {7,6,6}; slots {0,1,0}
    const int bases[3] = {0, 7, 13};
    const int cnts[3]  = {7, 6, 6};
    #pragma unroll 1
    for (int ip = 0; ip < 3; ip++) {
        asm volatile("cp.async.wait_group 0;");   // section ip resident
        __syncthreads();                          // target slot fully consumed

        if (ip < 2) {
            const int nb = bases[ip + 1];
            const int nc = cnts[ip + 1];
            const __half* src = g_w2h + nb * DCH_H;
            uint32_t dst = ((ip + 1) & 1) ? slot1 : slot0;
            const int units = nc * DCH_U;
            for (int u = tid; u < units; u += 512)
                cp16(dst + u * 16, src + u * 8);
            cp_commit();
        }

        const uint32_t sb = (ip & 1) ? slot1 : slot0;
        const int base = bases[ip];
        const int cnt  = cnts[ip];
        #pragma unroll
        for (int q = 0; q < 7; q++) {
            if (q < cnt) {
                CHUNK_MMA(base + q, sb + q * DCH_B);
            }
        }
    }

    // epilogue
    #pragma unroll
    for (int m = 0; m < 2; m++) {
        float rs0 = 0.f, rs1 = 0.f;
        #pragma unroll
        for (int t = 0; t < 10; t++) {
            int cb = (nq * 10 + t) * 8 + 2 * (lane & 3);
            #pragma unroll
            for (int q = 0; q < 2; q++) {
                int c = cb + q;
                rs0 += fmaxf(acc[m][t][q] + b2s[c], 0.f) * cws[c];
                rs1 += fmaxf(acc[m][t][2 + q] + b2s[c], 0.f) * cws[c];
            }
        }
        rs0 += __shfl_xor_sync(0xffffffffu, rs0, 1);
        rs0 += __shfl_xor_sync(0xffffffffu, rs0, 2);
        rs1 += __shfl_xor_sync(0xffffffffu, rs1, 1);
        rs1 += __shfl_xor_sync(0xffffffffu, rs1, 2);
        if ((lane & 3) == 0) {
            int rbase = r0 + m * 16 + (lane >> 2);
            atomicAdd(&outs[rbase], rs0);
            atomicAdd(&outs[rbase + 8], rs1);
        }
    }
    __syncthreads();
    if (tid < MT) {
        xmean[(b0 + tid) * DD + j] = outs[tid] + __ldg(col_b + j);
    }
}

// ---------------------------------------------------------------------------
// Launch
// ---------------------------------------------------------------------------
extern "C" void kernel_launch(void* const* d_in, const int* in_sizes, int n_in,
                              void* d_out, int out_size) {
    const float* x      = (const float*)d_in[0];
    const float* eps    = (const float*)d_in[1];
    const float* Wmask  = (const float*)d_in[2];
    const float* qz_w1  = (const float*)d_in[3];
    const float* qz_b1  = (const float*)d_in[4];
    const float* qz_w2  = (const float*)d_in[5];
    const float* qz_b2  = (const float*)d_in[6];
    const float* zm_w   = (const float*)d_in[7];
    const float* zm_b   = (const float*)d_in[8];
    const float* zl_w   = (const float*)d_in[9];
    const float* zl_b   = (const float*)d_in[10];
    const float* gen_w1 = (const float*)d_in[11];
    const float* gen_w2 = (const float*)d_in[12];
    const float* gen_b2 = (const float*)d_in[13];
    const float* col_w  = (const float*)d_in[14];
    const float* col_b  = (const float*)d_in[15];

    float* out    = (float*)d_out;
    float* xmean  = out;
    float* z_out  = out + BB * DD;
    float* zm_out = z_out + BB * LL;
    float* zl_out = zm_out + BB * LL;

    // Pack fp16 images (weights + x)
    {
        int total = DW1_H + 19 * DCH_H + (32 + 20) * CHUNK_H + NP * ZWS + BB * XRS;
        pack_weights<<<(total + 255) / 256, 256>>>(gen_w1, gen_w2, qz_w1,
                                                   qz_w2, zm_w, zl_w, x);
    }
    // enc1
    {
        cudaFuncSetAttribute(enc1_kernel,
                             cudaFuncAttributeMaxDynamicSharedMemorySize,
                             E1_SMEM);
        dim3 grid(8, 5);
        enc1_kernel<<<grid, 256, E1_SMEM>>>(qz_b1);
    }
    // enc2 + heads fused
    {
        cudaFuncSetAttribute(enc2_heads_kernel,
                             cudaFuncAttributeMaxDynamicSharedMemorySize,
                             E2_SMEM);
        enc2_heads_kernel<<<BB / 64, 512, E2_SMEM>>>(eps, qz_b2, zm_b, zl_b,
                                                     z_out, zm_out, zl_out);
    }
    // decoder
    {
        cudaFuncSetAttribute(decoder_kernel,
                             cudaFuncAttributeMaxDynamicSharedMemorySize,
                             SMEM_TOTAL);
        dim3 grid(BB / MT, DD);
        decoder_kernel<<<grid, 512, SMEM_TOTAL>>>(Wmask, gen_b2, col_w, col_b,
                                                  xmean);
    }
}